// round 13
// baseline (speedup 1.0000x reference)
#include <cuda_runtime.h>
#include <cuda_fp16.h>
#include <math.h>

#define N_NODES 100000
#define NUM_GRAPHS 128
#define H1 4
#define C1 48
#define F1 192   // H1*C1
#define C2 96
#define D_IN 128
#define NEG_SLOPE 0.2f
#define E_MAX 1750000   // raw edges (1.6M) + self loops (100k) with slack

// ---------------- scratch (device globals; no allocation) ----------------
__device__ __half g_h1h[N_NODES * F1];      // fp16 gather table (layer 1)
__device__ __half g_h1rh[N_NODES * F1];     // layer1 output (relu'd, fp16 -> GEMM2 A)
__device__ __half g_h2h[N_NODES * C2];      // fp16 gather table (layer 2)
__device__ float g_asrc1[N_NODES * H1];
__device__ float g_adst1[N_NODES * H1];
__device__ float g_asrc2[N_NODES];
__device__ float g_adst2[N_NODES];
__device__ float g_pool[NUM_GRAPHS * C2];
__device__ float g_cnt[NUM_GRAPHS];
__device__ int g_src[E_MAX];
__device__ int g_dst[E_MAX];
__device__ int g_batch[N_NODES];
__device__ int g_is64;
__device__ int g_deg[N_NODES];
__device__ int g_off[N_NODES + 1];
__device__ int g_cur[N_NODES];
__device__ int g_csr_src[E_MAX];
__device__ float g_p[E_MAX * H1];

__device__ __forceinline__ float leaky(float s) {
    return s > 0.0f ? s : NEG_SLOPE * s;
}

// ---------------- init (zero counters only; stream B) ----------------
__global__ void init_kernel() {
    int i = blockIdx.x * blockDim.x + threadIdx.x;
    int stride = gridDim.x * blockDim.x;
    for (int k = i; k < N_NODES; k += stride) g_deg[k] = 0;
    for (int k = i; k < NUM_GRAPHS * C2; k += stride) g_pool[k] = 0.0f;
    for (int k = i; k < NUM_GRAPHS; k += stride) g_cnt[k] = 0.0f;
}

// zero attention accumulators (default stream, before GEMM1)
__global__ void zero_attn_kernel() {
    int i = blockIdx.x * blockDim.x + threadIdx.x;
    if (i < N_NODES * H1) {
        g_asrc1[i] = 0.0f;
        g_adst1[i] = 0.0f;
    }
    if (i < N_NODES) {
        g_asrc2[i] = 0.0f;
        g_adst2[i] = 0.0f;
    }
}

// ---------------- dtype sniff: int64 vs int32 index buffers ----------------
__global__ void sniff_kernel(const unsigned int* __restrict__ w) {
    __shared__ int any_nonzero;
    if (threadIdx.x == 0) any_nonzero = 0;
    __syncthreads();
    for (int i = threadIdx.x; i < 256; i += blockDim.x) {
        if (w[2 * i + 1] != 0u) any_nonzero = 1;
    }
    __syncthreads();
    if (threadIdx.x == 0) g_is64 = (any_nonzero == 0) ? 1 : 0;
}

__global__ void decode_edges(const void* __restrict__ ei_raw, int E0) {
    int e = blockIdx.x * blockDim.x + threadIdx.x;
    int Etot = E0 + N_NODES;
    if (e >= Etot) return;
    int src, dst;
    if (e < E0) {
        if (g_is64) {
            const long long* p = (const long long*)ei_raw;
            src = (int)p[e];
            dst = (int)p[E0 + e];
        } else {
            const int* p = (const int*)ei_raw;
            src = p[e];
            dst = p[E0 + e];
        }
    } else {
        src = dst = e - E0;
    }
    g_src[e] = src;
    g_dst[e] = dst;
    atomicAdd(&g_deg[dst], 1);
}

__global__ void decode_batch(const void* __restrict__ b_raw) {
    __shared__ int hist[NUM_GRAPHS];
    for (int i = threadIdx.x; i < NUM_GRAPHS; i += blockDim.x) hist[i] = 0;
    __syncthreads();
    int n = blockIdx.x * blockDim.x + threadIdx.x;
    if (n < N_NODES) {
        int b = g_is64 ? (int)((const long long*)b_raw)[n] : ((const int*)b_raw)[n];
        g_batch[n] = b;
        atomicAdd(&hist[b], 1);
    }
    __syncthreads();
    for (int i = threadIdx.x; i < NUM_GRAPHS; i += blockDim.x)
        if (hist[i]) atomicAdd(&g_cnt[i], (float)hist[i]);
}

__global__ void scan_kernel() {
    __shared__ int part[1024];
    int t = threadIdx.x;
    const int CH = (N_NODES + 1023) / 1024;
    int lo = t * CH, hi = min(lo + CH, N_NODES);
    int s = 0;
    for (int i = lo; i < hi; i++) s += g_deg[i];
    part[t] = s;
    __syncthreads();
    for (int o = 1; o < 1024; o <<= 1) {
        int v = (t >= o) ? part[t - o] : 0;
        __syncthreads();
        part[t] += v;
        __syncthreads();
    }
    int base = (t > 0) ? part[t - 1] : 0;
    for (int i = lo; i < hi; i++) {
        g_off[i] = base;
        g_cur[i] = base;
        base += g_deg[i];
    }
    if (t == 1023) g_off[N_NODES] = part[1023];
}

__global__ void scatter_kernel(int Etot) {
    int e = blockIdx.x * blockDim.x + threadIdx.x;
    if (e >= Etot) return;
    int pos = atomicAdd(&g_cur[g_dst[e]], 1);
    g_csr_src[pos] = g_src[e];
}

// ---------------- GEMM1: [M,128]@[128,192] -> fp16 table + fused attn1 ------
__global__ void __launch_bounds__(256) sgemm1_kernel(const float* __restrict__ A,
                                                     const float* __restrict__ B,
                                                     __half* __restrict__ Ch,
                                                     const float* __restrict__ a_src,
                                                     const float* __restrict__ a_dst,
                                                     int M) {
    const int TBM = 128, TBN = 64, TBK = 32, N = F1, K = D_IN;
    __shared__ float As[TBK][TBM + 4];   // reused for attn reduce
    __shared__ float Bs[TBK][TBN + 4];

    int tid = threadIdx.x;
    int row0 = blockIdx.y * TBM;
    int col0 = blockIdx.x * TBN;
    int tx = tid % 16;
    int ty = tid / 16;

    float acc[8][4];
#pragma unroll
    for (int i = 0; i < 8; i++)
#pragma unroll
        for (int j = 0; j < 4; j++) acc[i][j] = 0.0f;

    for (int k0 = 0; k0 < K; k0 += TBK) {
#pragma unroll
        for (int it = 0; it < 4; it++) {
            int idA = tid + it * 256;
            int kc = idA % 8;
            int r = idA / 8;
            int gr = row0 + r;
            float4 v = (gr < M) ? *(const float4*)&A[(size_t)gr * K + k0 + kc * 4]
                                : make_float4(0.f, 0.f, 0.f, 0.f);
            As[kc * 4 + 0][r] = v.x;
            As[kc * 4 + 1][r] = v.y;
            As[kc * 4 + 2][r] = v.z;
            As[kc * 4 + 3][r] = v.w;
        }
#pragma unroll
        for (int it = 0; it < 2; it++) {
            int idB = tid + it * 256;
            int c4 = idB % 16;
            int r = idB / 16;
            *(float4*)&Bs[r][c4 * 4] = *(const float4*)&B[(size_t)(k0 + r) * N + col0 + c4 * 4];
        }
        __syncthreads();

#pragma unroll
        for (int k = 0; k < TBK; k++) {
            float4 a0 = *(const float4*)&As[k][ty * 8];
            float4 a1 = *(const float4*)&As[k][ty * 8 + 4];
            float4 b = *(const float4*)&Bs[k][tx * 4];
            float av[8] = {a0.x, a0.y, a0.z, a0.w, a1.x, a1.y, a1.z, a1.w};
            float bv[4] = {b.x, b.y, b.z, b.w};
#pragma unroll
            for (int i = 0; i < 8; i++)
#pragma unroll
                for (int j = 0; j < 4; j++) acc[i][j] += av[i] * bv[j];
        }
        __syncthreads();
    }

#pragma unroll
    for (int i = 0; i < 8; i++) {
        int gr = row0 + ty * 8 + i;
        if (gr < M) {
            __half2 h01 = __floats2half2_rn(acc[i][0], acc[i][1]);
            __half2 h23 = __floats2half2_rn(acc[i][2], acc[i][3]);
            *(__half2*)&Ch[(size_t)gr * N + col0 + tx * 4] = h01;
            *(__half2*)&Ch[(size_t)gr * N + col0 + tx * 4 + 2] = h23;
        }
    }

    // fused attention partials
    int cbase = col0 + tx * 4;
    float asv[4], adv[4];
#pragma unroll
    for (int j = 0; j < 4; j++) {
        asv[j] = a_src[cbase + j];
        adv[j] = a_dst[cbase + j];
    }
    float* sredS = &As[0][0];          // [128][16]
    float* sredD = sredS + 2048;
#pragma unroll
    for (int i = 0; i < 8; i++) {
        float ps = acc[i][0] * asv[0] + acc[i][1] * asv[1] + acc[i][2] * asv[2] + acc[i][3] * asv[3];
        float pd = acc[i][0] * adv[0] + acc[i][1] * adv[1] + acc[i][2] * adv[2] + acc[i][3] * adv[3];
        sredS[(ty * 8 + i) * 16 + tx] = ps;
        sredD[(ty * 8 + i) * 16 + tx] = pd;
    }
    __syncthreads();

    if (tid < 128) {
        int gr = row0 + tid;
        if (gr < M) {
            int h0 = col0 / 48;
            int gb = (48 * (h0 + 1) - col0) / 4;
            if (gb > 16) gb = 16;
            float s0 = 0.f, d0 = 0.f, s1 = 0.f, d1 = 0.f;
            for (int g = 0; g < gb; g++) {
                s0 += sredS[tid * 16 + g];
                d0 += sredD[tid * 16 + g];
            }
            for (int g = gb; g < 16; g++) {
                s1 += sredS[tid * 16 + g];
                d1 += sredD[tid * 16 + g];
            }
            atomicAdd(&g_asrc1[gr * H1 + h0], s0);
            atomicAdd(&g_adst1[gr * H1 + h0], d0);
            if (gb < 16) {
                atomicAdd(&g_asrc1[gr * H1 + h0 + 1], s1);
                atomicAdd(&g_adst1[gr * H1 + h0 + 1], d1);
            }
        }
    }
}

// ---------------- GEMM2: [rows,192](fp16)@[192,96] -> fp16 table + fused attn2
// Chunked by rows: row0 = row_off + blockIdx.y*TBM; guard with lim.
__global__ void __launch_bounds__(256) sgemm2_kernel(const __half* __restrict__ A,
                                                     const float* __restrict__ B,
                                                     __half* __restrict__ Ch,
                                                     const float* __restrict__ a_src,
                                                     const float* __restrict__ a_dst,
                                                     int row_off, int lim) {
    const int TBM = 256, TBN = 32, TBK = 32, N = C2, K = F1;
    __shared__ float As[TBK][TBM + 4];
    __shared__ float Bs[TBK][TBN + 4];

    int tid = threadIdx.x;
    int row0 = row_off + blockIdx.y * TBM;
    int col0 = blockIdx.x * TBN;
    int tx = tid % 8;
    int ty = tid / 8;

    float acc[8][4];
#pragma unroll
    for (int i = 0; i < 8; i++)
#pragma unroll
        for (int j = 0; j < 4; j++) acc[i][j] = 0.0f;

    for (int k0 = 0; k0 < K; k0 += TBK) {
#pragma unroll
        for (int it = 0; it < 8; it++) {
            int idA = tid + it * 256;
            int kc = idA % 8;
            int r = idA / 8;
            int gr = row0 + r;
            float4 v = make_float4(0.f, 0.f, 0.f, 0.f);
            if (gr < lim) {
                const __half2* ap = (const __half2*)&A[(size_t)gr * K + k0 + kc * 4];
                float2 f0 = __half22float2(ap[0]);
                float2 f1 = __half22float2(ap[1]);
                v = make_float4(f0.x, f0.y, f1.x, f1.y);
            }
            As[kc * 4 + 0][r] = v.x;
            As[kc * 4 + 1][r] = v.y;
            As[kc * 4 + 2][r] = v.z;
            As[kc * 4 + 3][r] = v.w;
        }
        {
            int c4 = tid % 8;
            int r = tid / 8;
            *(float4*)&Bs[r][c4 * 4] = *(const float4*)&B[(size_t)(k0 + r) * N + col0 + c4 * 4];
        }
        __syncthreads();

#pragma unroll
        for (int k = 0; k < TBK; k++) {
            float4 a0 = *(const float4*)&As[k][ty * 8];
            float4 a1 = *(const float4*)&As[k][ty * 8 + 4];
            float4 b = *(const float4*)&Bs[k][tx * 4];
            float av[8] = {a0.x, a0.y, a0.z, a0.w, a1.x, a1.y, a1.z, a1.w};
            float bv[4] = {b.x, b.y, b.z, b.w};
#pragma unroll
            for (int i = 0; i < 8; i++)
#pragma unroll
                for (int j = 0; j < 4; j++) acc[i][j] += av[i] * bv[j];
        }
        __syncthreads();
    }

    int cbase = col0 + tx * 4;
    float asv[4], adv[4];
#pragma unroll
    for (int j = 0; j < 4; j++) {
        asv[j] = a_src[cbase + j];
        adv[j] = a_dst[cbase + j];
    }

#pragma unroll
    for (int i = 0; i < 8; i++) {
        int gr = row0 + ty * 8 + i;
        float ps = acc[i][0] * asv[0] + acc[i][1] * asv[1] + acc[i][2] * asv[2] + acc[i][3] * asv[3];
        float pd = acc[i][0] * adv[0] + acc[i][1] * adv[1] + acc[i][2] * adv[2] + acc[i][3] * adv[3];
#pragma unroll
        for (int o = 1; o < 8; o <<= 1) {
            ps += __shfl_xor_sync(0xffffffffu, ps, o);
            pd += __shfl_xor_sync(0xffffffffu, pd, o);
        }
        if (gr < lim) {
            __half2 h01 = __floats2half2_rn(acc[i][0], acc[i][1]);
            __half2 h23 = __floats2half2_rn(acc[i][2], acc[i][3]);
            *(__half2*)&Ch[(size_t)gr * N + col0 + tx * 4] = h01;
            *(__half2*)&Ch[(size_t)gr * N + col0 + tx * 4 + 2] = h23;
            if (tx == 0) {
                atomicAdd(&g_asrc2[gr], ps);
                atomicAdd(&g_adst2[gr], pd);
            }
        }
    }
}

// ---------------- layer 1 fused (chunked): fp32 softmax, fp16 gather --------
__global__ void gat1_kernel(const float* __restrict__ b1, int node_off, int node_lim) {
    int node = node_off + ((blockIdx.x * blockDim.x + threadIdx.x) >> 5);
    int lane = threadIdx.x & 31;
    if (node >= node_lim) return;
    int start = g_off[node], end = g_off[node + 1];

    float4 ad = *(const float4*)&g_adst1[node * H1];

    float4 den = make_float4(0.f, 0.f, 0.f, 0.f);
    for (int idx = start + lane; idx < end; idx += 32) {
        int src = g_csr_src[idx];
        float4 as = *(const float4*)&g_asrc1[src * H1];
        float4 p;
        p.x = __expf(leaky(as.x + ad.x));
        p.y = __expf(leaky(as.y + ad.y));
        p.z = __expf(leaky(as.z + ad.z));
        p.w = __expf(leaky(as.w + ad.w));
        *(float4*)&g_p[(size_t)idx * 4] = p;
        den.x += p.x; den.y += p.y; den.z += p.z; den.w += p.w;
    }
#pragma unroll
    for (int o = 16; o > 0; o >>= 1) {
        den.x += __shfl_xor_sync(0xffffffffu, den.x, o);
        den.y += __shfl_xor_sync(0xffffffffu, den.y, o);
        den.z += __shfl_xor_sync(0xffffffffu, den.z, o);
        den.w += __shfl_xor_sync(0xffffffffu, den.w, o);
    }
    float inv0 = 1.0f / den.x, inv1 = 1.0f / den.y, inv2 = 1.0f / den.z, inv3 = 1.0f / den.w;

    float acc[6] = {0.f, 0.f, 0.f, 0.f, 0.f, 0.f};
    for (int idx = start; idx < end; idx++) {
        int src = g_csr_src[idx];
        float4 p4 = *(const float4*)&g_p[(size_t)idx * 4];
        float a0 = p4.x * inv0, a1 = p4.y * inv1, a2 = p4.z * inv2, a3 = p4.w * inv3;
        const __half* hp = &g_h1h[(size_t)src * F1];
#pragma unroll
        for (int k = 0; k < 6; k++) {
            int c = k * 32 + lane;
            float al = (c < 48) ? a0 : (c < 96) ? a1 : (c < 144) ? a2 : a3;
            acc[k] += __half2float(hp[c]) * al;
        }
    }
#pragma unroll
    for (int k = 0; k < 6; k++) {
        int c = k * 32 + lane;
        g_h1rh[(size_t)node * F1 + c] = __float2half(fmaxf(acc[k] + b1[c], 0.0f));
    }
}

// ---------------- layer 2 fused (R9-proven): fp32 softmax + pool ------------
__global__ void gat2_kernel(const float* __restrict__ b2) {
    int node = (blockIdx.x * blockDim.x + threadIdx.x) >> 5;
    int lane = threadIdx.x & 31;
    if (node >= N_NODES) return;
    int start = g_off[node], end = g_off[node + 1];

    float ad = g_adst2[node];
    float den = 0.0f;
    for (int idx = start + lane; idx < end; idx += 32) {
        int src = g_csr_src[idx];
        float p = __expf(leaky(g_asrc2[src] + ad));
        g_p[idx] = p;
        den += p;
    }
#pragma unroll
    for (int o = 16; o > 0; o >>= 1) den += __shfl_xor_sync(0xffffffffu, den, o);
    float inv = 1.0f / den;

    float acc[3] = {0.f, 0.f, 0.f};
    for (int idx = start; idx < end; idx++) {
        int src = g_csr_src[idx];
        float alpha = g_p[idx] * inv;
        const __half* hp = &g_h2h[(size_t)src * C2];
#pragma unroll
        for (int k = 0; k < 3; k++) acc[k] += __half2float(hp[k * 32 + lane]) * alpha;
    }
    int gp = g_batch[node] * C2;
#pragma unroll
    for (int k = 0; k < 3; k++) {
        int c = k * 32 + lane;
        float v = fmaxf(acc[k] + b2[c], 0.0f);
        atomicAdd(&g_pool[gp + c], v);
    }
}

// ---------------- final MLP: one block per graph ----------------
__global__ void mlp_kernel(const float* __restrict__ fc1_w, const float* __restrict__ fc1_b,
                           const float* __restrict__ fc2_w, const float* __restrict__ fc2_b,
                           float* __restrict__ out) {
    __shared__ float p[C2];
    __shared__ float z[192];
    int g = blockIdx.x;
    int t = threadIdx.x;
    float inv = 1.0f / fmaxf(g_cnt[g], 1.0f);
    if (t < C2) p[t] = g_pool[g * C2 + t] * inv;
    __syncthreads();
    float acc = fc1_b[t];
#pragma unroll
    for (int k = 0; k < C2; k++) acc += p[k] * fc1_w[k * 192 + t];
    z[t] = fmaxf(acc, 0.0f);
    __syncthreads();
    if (t < C2) {
        float o = fc2_b[t];
#pragma unroll
        for (int k = 0; k < 192; k++) o += z[k] * fc2_w[k * C2 + t];
        out[g * C2 + t] = o;
    }
}

// ---------------- host launch (two-stream + gat1/GEMM2 pipeline) ------------
extern "C" void kernel_launch(void* const* d_in, const int* in_sizes, int n_in,
                              void* d_out, int out_size) {
    const float* x = (const float*)d_in[0];
    const void* ei_raw = d_in[1];
    const void* batch_raw = d_in[2];
    const float* W1 = (const float*)d_in[3];
    const float* a_src1 = (const float*)d_in[4];
    const float* a_dst1 = (const float*)d_in[5];
    const float* b1 = (const float*)d_in[6];
    const float* W2 = (const float*)d_in[7];
    const float* a_src2 = (const float*)d_in[8];
    const float* a_dst2 = (const float*)d_in[9];
    const float* b2 = (const float*)d_in[10];
    const float* fc1_w = (const float*)d_in[11];
    const float* fc1_b = (const float*)d_in[12];
    const float* fc2_w = (const float*)d_in[13];
    const float* fc2_b = (const float*)d_in[14];
    float* out = (float*)d_out;

    int E0 = in_sizes[1] / 2;
    int Etot = E0 + N_NODES;

    __half *h1hp, *h1rhp, *h2hp;
    cudaGetSymbolAddress((void**)&h1hp, g_h1h);
    cudaGetSymbolAddress((void**)&h1rhp, g_h1rh);
    cudaGetSymbolAddress((void**)&h2hp, g_h2h);

    cudaStream_t sB;
    cudaStreamCreateWithFlags(&sB, cudaStreamNonBlocking);
    cudaEvent_t evFork, evJoin, evJ2;
    cudaEvent_t evG[4];
    cudaEventCreateWithFlags(&evFork, cudaEventDisableTiming);
    cudaEventCreateWithFlags(&evJoin, cudaEventDisableTiming);
    cudaEventCreateWithFlags(&evJ2, cudaEventDisableTiming);
    for (int i = 0; i < 4; i++) cudaEventCreateWithFlags(&evG[i], cudaEventDisableTiming);

    cudaEventRecord(evFork, 0);
    cudaStreamWaitEvent(sB, evFork, 0);

    // ---- stream B: CSR build + batch decode ----
    init_kernel<<<256, 256, 0, sB>>>();
    sniff_kernel<<<1, 256, 0, sB>>>((const unsigned int*)ei_raw);
    decode_edges<<<(Etot + 255) / 256, 256, 0, sB>>>(ei_raw, E0);
    decode_batch<<<(N_NODES + 255) / 256, 256, 0, sB>>>(batch_raw);
    scan_kernel<<<1, 1024, 0, sB>>>();
    scatter_kernel<<<(Etot + 255) / 256, 256, 0, sB>>>(Etot);
    cudaEventRecord(evJoin, sB);

    // ---- default: zero attn accumulators, GEMM1 (+fused attn1) ----
    zero_attn_kernel<<<(N_NODES * H1 + 255) / 256, 256>>>();
    {
        dim3 grid(F1 / 64, (N_NODES + 127) / 128);
        sgemm1_kernel<<<grid, 256>>>(x, W1, h1hp, a_src1, a_dst1, N_NODES);
    }
    cudaStreamWaitEvent(0, evJoin, 0);

    // ---- pipelined gat1 (default) / GEMM2 (stream B) over 4 node chunks ----
    const int starts[5] = {0, 25088, 50176, 75264, N_NODES};  // multiples of 256
    for (int i = 0; i < 4; i++) {
        int off = starts[i], lim = starts[i + 1];
        int cnt = lim - off;
        gat1_kernel<<<(cnt + 7) / 8, 256>>>(b1, off, lim);
        cudaEventRecord(evG[i], 0);
        cudaStreamWaitEvent(sB, evG[i], 0);
        dim3 grid(C2 / 32, (cnt + 255) / 256);
        sgemm2_kernel<<<grid, 256, 0, sB>>>(h1rhp, W2, h2hp, a_src2, a_dst2, off, lim);
    }
    cudaEventRecord(evJ2, sB);
    cudaStreamWaitEvent(0, evJ2, 0);

    // ---- default: gat2, MLP ----
    gat2_kernel<<<(N_NODES + 7) / 8, 256>>>(b2);
    mlp_kernel<<<NUM_GRAPHS, 192>>>(fc1_w, fc1_b, fc2_w, fc2_b, out);
}

// round 14
// speedup vs baseline: 1.0273x; 1.0273x over previous
#include <cuda_runtime.h>
#include <cuda_fp16.h>
#include <math.h>

#define N_NODES 100000
#define NUM_GRAPHS 128
#define H1 4
#define C1 48
#define F1 192   // H1*C1
#define C2 96
#define D_IN 128
#define NEG_SLOPE 0.2f
#define E_MAX 1750000   // raw edges (1.6M) + self loops (100k) with slack

// ---------------- scratch (device globals; no allocation) ----------------
__device__ __half g_h1h[N_NODES * F1];      // fp16 gather table (layer 1)
__device__ __half g_h1rh[N_NODES * F1];     // layer1 output (relu'd, fp16 -> GEMM2 A)
__device__ __half g_h2h[N_NODES * C2];      // fp16 gather table (layer 2)
__device__ float g_asrc1[N_NODES * H1];
__device__ float g_adst1[N_NODES * H1];
__device__ float g_asrc2[N_NODES];
__device__ float g_adst2[N_NODES];
__device__ float g_pool[NUM_GRAPHS * C2];
__device__ float g_cnt[NUM_GRAPHS];
__device__ int g_src[E_MAX];
__device__ int g_dst[E_MAX];
__device__ int g_batch[N_NODES];
__device__ int g_is64;
__device__ int g_deg[N_NODES];
__device__ int g_off[N_NODES + 1];
__device__ int g_cur[N_NODES];
__device__ int g_csr_src[E_MAX];
__device__ float g_p[E_MAX * H1];

__device__ __forceinline__ float leaky(float s) {
    return s > 0.0f ? s : NEG_SLOPE * s;
}

// ---------------- init (zero counters only; stream B) ----------------
__global__ void init_kernel() {
    int i = blockIdx.x * blockDim.x + threadIdx.x;
    int stride = gridDim.x * blockDim.x;
    for (int k = i; k < N_NODES; k += stride) g_deg[k] = 0;
    for (int k = i; k < NUM_GRAPHS * C2; k += stride) g_pool[k] = 0.0f;
    for (int k = i; k < NUM_GRAPHS; k += stride) g_cnt[k] = 0.0f;
}

// zero attention accumulators (default stream, before GEMM1)
__global__ void zero_attn_kernel() {
    int i = blockIdx.x * blockDim.x + threadIdx.x;
    if (i < N_NODES * H1) {
        g_asrc1[i] = 0.0f;
        g_adst1[i] = 0.0f;
    }
    if (i < N_NODES) {
        g_asrc2[i] = 0.0f;
        g_adst2[i] = 0.0f;
    }
}

// ---------------- dtype sniff: int64 vs int32 index buffers ----------------
__global__ void sniff_kernel(const unsigned int* __restrict__ w) {
    __shared__ int any_nonzero;
    if (threadIdx.x == 0) any_nonzero = 0;
    __syncthreads();
    for (int i = threadIdx.x; i < 256; i += blockDim.x) {
        if (w[2 * i + 1] != 0u) any_nonzero = 1;
    }
    __syncthreads();
    if (threadIdx.x == 0) g_is64 = (any_nonzero == 0) ? 1 : 0;
}

__global__ void decode_edges(const void* __restrict__ ei_raw, int E0) {
    int e = blockIdx.x * blockDim.x + threadIdx.x;
    int Etot = E0 + N_NODES;
    if (e >= Etot) return;
    int src, dst;
    if (e < E0) {
        if (g_is64) {
            const long long* p = (const long long*)ei_raw;
            src = (int)p[e];
            dst = (int)p[E0 + e];
        } else {
            const int* p = (const int*)ei_raw;
            src = p[e];
            dst = p[E0 + e];
        }
    } else {
        src = dst = e - E0;
    }
    g_src[e] = src;
    g_dst[e] = dst;
    atomicAdd(&g_deg[dst], 1);
}

__global__ void decode_batch(const void* __restrict__ b_raw) {
    __shared__ int hist[NUM_GRAPHS];
    for (int i = threadIdx.x; i < NUM_GRAPHS; i += blockDim.x) hist[i] = 0;
    __syncthreads();
    int n = blockIdx.x * blockDim.x + threadIdx.x;
    if (n < N_NODES) {
        int b = g_is64 ? (int)((const long long*)b_raw)[n] : ((const int*)b_raw)[n];
        g_batch[n] = b;
        atomicAdd(&hist[b], 1);
    }
    __syncthreads();
    for (int i = threadIdx.x; i < NUM_GRAPHS; i += blockDim.x)
        if (hist[i]) atomicAdd(&g_cnt[i], (float)hist[i]);
}

__global__ void scan_kernel() {
    __shared__ int part[1024];
    int t = threadIdx.x;
    const int CH = (N_NODES + 1023) / 1024;
    int lo = t * CH, hi = min(lo + CH, N_NODES);
    int s = 0;
    for (int i = lo; i < hi; i++) s += g_deg[i];
    part[t] = s;
    __syncthreads();
    for (int o = 1; o < 1024; o <<= 1) {
        int v = (t >= o) ? part[t - o] : 0;
        __syncthreads();
        part[t] += v;
        __syncthreads();
    }
    int base = (t > 0) ? part[t - 1] : 0;
    for (int i = lo; i < hi; i++) {
        g_off[i] = base;
        g_cur[i] = base;
        base += g_deg[i];
    }
    if (t == 1023) g_off[N_NODES] = part[1023];
}

__global__ void scatter_kernel(int Etot) {
    int e = blockIdx.x * blockDim.x + threadIdx.x;
    if (e >= Etot) return;
    int pos = atomicAdd(&g_cur[g_dst[e]], 1);
    g_csr_src[pos] = g_src[e];
}

// ---------------- GEMM1: [M,128]@[128,192] -> fp16 table + fused attn1 ------
__global__ void __launch_bounds__(256) sgemm1_kernel(const float* __restrict__ A,
                                                     const float* __restrict__ B,
                                                     __half* __restrict__ Ch,
                                                     const float* __restrict__ a_src,
                                                     const float* __restrict__ a_dst,
                                                     int M) {
    const int TBM = 128, TBN = 64, TBK = 32, N = F1, K = D_IN;
    __shared__ float As[TBK][TBM + 4];   // reused for attn reduce
    __shared__ float Bs[TBK][TBN + 4];

    int tid = threadIdx.x;
    int row0 = blockIdx.y * TBM;
    int col0 = blockIdx.x * TBN;
    int tx = tid % 16;
    int ty = tid / 16;

    float acc[8][4];
#pragma unroll
    for (int i = 0; i < 8; i++)
#pragma unroll
        for (int j = 0; j < 4; j++) acc[i][j] = 0.0f;

    for (int k0 = 0; k0 < K; k0 += TBK) {
#pragma unroll
        for (int it = 0; it < 4; it++) {
            int idA = tid + it * 256;
            int kc = idA % 8;
            int r = idA / 8;
            int gr = row0 + r;
            float4 v = (gr < M) ? *(const float4*)&A[(size_t)gr * K + k0 + kc * 4]
                                : make_float4(0.f, 0.f, 0.f, 0.f);
            As[kc * 4 + 0][r] = v.x;
            As[kc * 4 + 1][r] = v.y;
            As[kc * 4 + 2][r] = v.z;
            As[kc * 4 + 3][r] = v.w;
        }
#pragma unroll
        for (int it = 0; it < 2; it++) {
            int idB = tid + it * 256;
            int c4 = idB % 16;
            int r = idB / 16;
            *(float4*)&Bs[r][c4 * 4] = *(const float4*)&B[(size_t)(k0 + r) * N + col0 + c4 * 4];
        }
        __syncthreads();

#pragma unroll
        for (int k = 0; k < TBK; k++) {
            float4 a0 = *(const float4*)&As[k][ty * 8];
            float4 a1 = *(const float4*)&As[k][ty * 8 + 4];
            float4 b = *(const float4*)&Bs[k][tx * 4];
            float av[8] = {a0.x, a0.y, a0.z, a0.w, a1.x, a1.y, a1.z, a1.w};
            float bv[4] = {b.x, b.y, b.z, b.w};
#pragma unroll
            for (int i = 0; i < 8; i++)
#pragma unroll
                for (int j = 0; j < 4; j++) acc[i][j] += av[i] * bv[j];
        }
        __syncthreads();
    }

#pragma unroll
    for (int i = 0; i < 8; i++) {
        int gr = row0 + ty * 8 + i;
        if (gr < M) {
            __half2 h01 = __floats2half2_rn(acc[i][0], acc[i][1]);
            __half2 h23 = __floats2half2_rn(acc[i][2], acc[i][3]);
            *(__half2*)&Ch[(size_t)gr * N + col0 + tx * 4] = h01;
            *(__half2*)&Ch[(size_t)gr * N + col0 + tx * 4 + 2] = h23;
        }
    }

    // fused attention partials
    int cbase = col0 + tx * 4;
    float asv[4], adv[4];
#pragma unroll
    for (int j = 0; j < 4; j++) {
        asv[j] = a_src[cbase + j];
        adv[j] = a_dst[cbase + j];
    }
    float* sredS = &As[0][0];          // [128][16]
    float* sredD = sredS + 2048;
#pragma unroll
    for (int i = 0; i < 8; i++) {
        float ps = acc[i][0] * asv[0] + acc[i][1] * asv[1] + acc[i][2] * asv[2] + acc[i][3] * asv[3];
        float pd = acc[i][0] * adv[0] + acc[i][1] * adv[1] + acc[i][2] * adv[2] + acc[i][3] * adv[3];
        sredS[(ty * 8 + i) * 16 + tx] = ps;
        sredD[(ty * 8 + i) * 16 + tx] = pd;
    }
    __syncthreads();

    if (tid < 128) {
        int gr = row0 + tid;
        if (gr < M) {
            int h0 = col0 / 48;
            int gb = (48 * (h0 + 1) - col0) / 4;
            if (gb > 16) gb = 16;
            float s0 = 0.f, d0 = 0.f, s1 = 0.f, d1 = 0.f;
            for (int g = 0; g < gb; g++) {
                s0 += sredS[tid * 16 + g];
                d0 += sredD[tid * 16 + g];
            }
            for (int g = gb; g < 16; g++) {
                s1 += sredS[tid * 16 + g];
                d1 += sredD[tid * 16 + g];
            }
            atomicAdd(&g_asrc1[gr * H1 + h0], s0);
            atomicAdd(&g_adst1[gr * H1 + h0], d0);
            if (gb < 16) {
                atomicAdd(&g_asrc1[gr * H1 + h0 + 1], s1);
                atomicAdd(&g_adst1[gr * H1 + h0 + 1], d1);
            }
        }
    }
}

// ---------------- GEMM2: [M,192](fp16)@[192,96] -> fp16 table + fused attn2 -
__global__ void __launch_bounds__(256) sgemm2_kernel(const __half* __restrict__ A,
                                                     const float* __restrict__ B,
                                                     __half* __restrict__ Ch,
                                                     const float* __restrict__ a_src,
                                                     const float* __restrict__ a_dst,
                                                     int M) {
    const int TBM = 256, TBN = 32, TBK = 32, N = C2, K = F1;
    __shared__ float As[TBK][TBM + 4];
    __shared__ float Bs[TBK][TBN + 4];

    int tid = threadIdx.x;
    int row0 = blockIdx.y * TBM;
    int col0 = blockIdx.x * TBN;
    int tx = tid % 8;
    int ty = tid / 8;

    float acc[8][4];
#pragma unroll
    for (int i = 0; i < 8; i++)
#pragma unroll
        for (int j = 0; j < 4; j++) acc[i][j] = 0.0f;

    for (int k0 = 0; k0 < K; k0 += TBK) {
#pragma unroll
        for (int it = 0; it < 8; it++) {
            int idA = tid + it * 256;
            int kc = idA % 8;
            int r = idA / 8;
            int gr = row0 + r;
            float4 v = make_float4(0.f, 0.f, 0.f, 0.f);
            if (gr < M) {
                const __half2* ap = (const __half2*)&A[(size_t)gr * K + k0 + kc * 4];
                float2 f0 = __half22float2(ap[0]);
                float2 f1 = __half22float2(ap[1]);
                v = make_float4(f0.x, f0.y, f1.x, f1.y);
            }
            As[kc * 4 + 0][r] = v.x;
            As[kc * 4 + 1][r] = v.y;
            As[kc * 4 + 2][r] = v.z;
            As[kc * 4 + 3][r] = v.w;
        }
        {
            int c4 = tid % 8;
            int r = tid / 8;
            *(float4*)&Bs[r][c4 * 4] = *(const float4*)&B[(size_t)(k0 + r) * N + col0 + c4 * 4];
        }
        __syncthreads();

#pragma unroll
        for (int k = 0; k < TBK; k++) {
            float4 a0 = *(const float4*)&As[k][ty * 8];
            float4 a1 = *(const float4*)&As[k][ty * 8 + 4];
            float4 b = *(const float4*)&Bs[k][tx * 4];
            float av[8] = {a0.x, a0.y, a0.z, a0.w, a1.x, a1.y, a1.z, a1.w};
            float bv[4] = {b.x, b.y, b.z, b.w};
#pragma unroll
            for (int i = 0; i < 8; i++)
#pragma unroll
                for (int j = 0; j < 4; j++) acc[i][j] += av[i] * bv[j];
        }
        __syncthreads();
    }

    int cbase = col0 + tx * 4;
    float asv[4], adv[4];
#pragma unroll
    for (int j = 0; j < 4; j++) {
        asv[j] = a_src[cbase + j];
        adv[j] = a_dst[cbase + j];
    }

#pragma unroll
    for (int i = 0; i < 8; i++) {
        int gr = row0 + ty * 8 + i;
        float ps = acc[i][0] * asv[0] + acc[i][1] * asv[1] + acc[i][2] * asv[2] + acc[i][3] * asv[3];
        float pd = acc[i][0] * adv[0] + acc[i][1] * adv[1] + acc[i][2] * adv[2] + acc[i][3] * adv[3];
#pragma unroll
        for (int o = 1; o < 8; o <<= 1) {
            ps += __shfl_xor_sync(0xffffffffu, ps, o);
            pd += __shfl_xor_sync(0xffffffffu, pd, o);
        }
        if (gr < M) {
            __half2 h01 = __floats2half2_rn(acc[i][0], acc[i][1]);
            __half2 h23 = __floats2half2_rn(acc[i][2], acc[i][3]);
            *(__half2*)&Ch[(size_t)gr * N + col0 + tx * 4] = h01;
            *(__half2*)&Ch[(size_t)gr * N + col0 + tx * 4 + 2] = h23;
            if (tx == 0) {
                atomicAdd(&g_asrc2[gr], ps);
                atomicAdd(&g_adst2[gr], pd);
            }
        }
    }
}

// ---------------- layer 1 fused: fp32 softmax, fp16 gather, fp16 output -----
__global__ void gat1_kernel(const float* __restrict__ b1) {
    int node = (blockIdx.x * blockDim.x + threadIdx.x) >> 5;
    int lane = threadIdx.x & 31;
    if (node >= N_NODES) return;
    int start = g_off[node], end = g_off[node + 1];

    float4 ad = *(const float4*)&g_adst1[node * H1];

    float4 den = make_float4(0.f, 0.f, 0.f, 0.f);
    for (int idx = start + lane; idx < end; idx += 32) {
        int src = g_csr_src[idx];
        float4 as = *(const float4*)&g_asrc1[src * H1];
        float4 p;
        p.x = __expf(leaky(as.x + ad.x));
        p.y = __expf(leaky(as.y + ad.y));
        p.z = __expf(leaky(as.z + ad.z));
        p.w = __expf(leaky(as.w + ad.w));
        *(float4*)&g_p[(size_t)idx * 4] = p;
        den.x += p.x; den.y += p.y; den.z += p.z; den.w += p.w;
    }
#pragma unroll
    for (int o = 16; o > 0; o >>= 1) {
        den.x += __shfl_xor_sync(0xffffffffu, den.x, o);
        den.y += __shfl_xor_sync(0xffffffffu, den.y, o);
        den.z += __shfl_xor_sync(0xffffffffu, den.z, o);
        den.w += __shfl_xor_sync(0xffffffffu, den.w, o);
    }
    float inv0 = 1.0f / den.x, inv1 = 1.0f / den.y, inv2 = 1.0f / den.z, inv3 = 1.0f / den.w;

    float acc[6] = {0.f, 0.f, 0.f, 0.f, 0.f, 0.f};
    for (int idx = start; idx < end; idx++) {
        int src = g_csr_src[idx];
        float4 p4 = *(const float4*)&g_p[(size_t)idx * 4];
        float a0 = p4.x * inv0, a1 = p4.y * inv1, a2 = p4.z * inv2, a3 = p4.w * inv3;
        const __half* hp = &g_h1h[(size_t)src * F1];
#pragma unroll
        for (int k = 0; k < 6; k++) {
            int c = k * 32 + lane;
            float al = (c < 48) ? a0 : (c < 96) ? a1 : (c < 144) ? a2 : a3;
            acc[k] += __half2float(hp[c]) * al;
        }
    }
#pragma unroll
    for (int k = 0; k < 6; k++) {
        int c = k * 32 + lane;
        g_h1rh[(size_t)node * F1 + c] = __float2half(fmaxf(acc[k] + b1[c], 0.0f));
    }
}

// ---------------- layer 2 fused: fp32 softmax + pool ------------------------
__global__ void gat2_kernel(const float* __restrict__ b2) {
    int node = (blockIdx.x * blockDim.x + threadIdx.x) >> 5;
    int lane = threadIdx.x & 31;
    if (node >= N_NODES) return;
    int start = g_off[node], end = g_off[node + 1];

    float ad = g_adst2[node];
    float den = 0.0f;
    for (int idx = start + lane; idx < end; idx += 32) {
        int src = g_csr_src[idx];
        float p = __expf(leaky(g_asrc2[src] + ad));
        g_p[idx] = p;
        den += p;
    }
#pragma unroll
    for (int o = 16; o > 0; o >>= 1) den += __shfl_xor_sync(0xffffffffu, den, o);
    float inv = 1.0f / den;

    float acc[3] = {0.f, 0.f, 0.f};
    for (int idx = start; idx < end; idx++) {
        int src = g_csr_src[idx];
        float alpha = g_p[idx] * inv;
        const __half* hp = &g_h2h[(size_t)src * C2];
#pragma unroll
        for (int k = 0; k < 3; k++) acc[k] += __half2float(hp[k * 32 + lane]) * alpha;
    }
    int gp = g_batch[node] * C2;
#pragma unroll
    for (int k = 0; k < 3; k++) {
        int c = k * 32 + lane;
        float v = fmaxf(acc[k] + b2[c], 0.0f);
        atomicAdd(&g_pool[gp + c], v);
    }
}

// ---------------- final MLP: one block per graph ----------------
__global__ void mlp_kernel(const float* __restrict__ fc1_w, const float* __restrict__ fc1_b,
                           const float* __restrict__ fc2_w, const float* __restrict__ fc2_b,
                           float* __restrict__ out) {
    __shared__ float p[C2];
    __shared__ float z[192];
    int g = blockIdx.x;
    int t = threadIdx.x;
    float inv = 1.0f / fmaxf(g_cnt[g], 1.0f);
    if (t < C2) p[t] = g_pool[g * C2 + t] * inv;
    __syncthreads();
    float acc = fc1_b[t];
#pragma unroll
    for (int k = 0; k < C2; k++) acc += p[k] * fc1_w[k * 192 + t];
    z[t] = fmaxf(acc, 0.0f);
    __syncthreads();
    if (t < C2) {
        float o = fc2_b[t];
#pragma unroll
        for (int k = 0; k < 192; k++) o += z[k] * fc2_w[k * C2 + t];
        out[g * C2 + t] = o;
    }
}

// ---------------- host launch (R12-proven two-stream structure) -------------
extern "C" void kernel_launch(void* const* d_in, const int* in_sizes, int n_in,
                              void* d_out, int out_size) {
    const float* x = (const float*)d_in[0];
    const void* ei_raw = d_in[1];
    const void* batch_raw = d_in[2];
    const float* W1 = (const float*)d_in[3];
    const float* a_src1 = (const float*)d_in[4];
    const float* a_dst1 = (const float*)d_in[5];
    const float* b1 = (const float*)d_in[6];
    const float* W2 = (const float*)d_in[7];
    const float* a_src2 = (const float*)d_in[8];
    const float* a_dst2 = (const float*)d_in[9];
    const float* b2 = (const float*)d_in[10];
    const float* fc1_w = (const float*)d_in[11];
    const float* fc1_b = (const float*)d_in[12];
    const float* fc2_w = (const float*)d_in[13];
    const float* fc2_b = (const float*)d_in[14];
    float* out = (float*)d_out;

    int E0 = in_sizes[1] / 2;
    int Etot = E0 + N_NODES;

    __half *h1hp, *h1rhp, *h2hp;
    cudaGetSymbolAddress((void**)&h1hp, g_h1h);
    cudaGetSymbolAddress((void**)&h1rhp, g_h1rh);
    cudaGetSymbolAddress((void**)&h2hp, g_h2h);

    cudaStream_t sB;
    cudaStreamCreateWithFlags(&sB, cudaStreamNonBlocking);
    cudaEvent_t evFork, evJoin;
    cudaEventCreateWithFlags(&evFork, cudaEventDisableTiming);
    cudaEventCreateWithFlags(&evJoin, cudaEventDisableTiming);

    cudaEventRecord(evFork, 0);
    cudaStreamWaitEvent(sB, evFork, 0);

    // ---- stream B: CSR build + batch decode ----
    init_kernel<<<256, 256, 0, sB>>>();
    sniff_kernel<<<1, 256, 0, sB>>>((const unsigned int*)ei_raw);
    decode_edges<<<(Etot + 255) / 256, 256, 0, sB>>>(ei_raw, E0);
    decode_batch<<<(N_NODES + 255) / 256, 256, 0, sB>>>(batch_raw);
    scan_kernel<<<1, 1024, 0, sB>>>();
    scatter_kernel<<<(Etot + 255) / 256, 256, 0, sB>>>(Etot);
    cudaEventRecord(evJoin, sB);

    // ---- default: zero attn accumulators, GEMM1 (+fused attn1) ----
    zero_attn_kernel<<<(N_NODES * H1 + 255) / 256, 256>>>();
    {
        dim3 grid(F1 / 64, (N_NODES + 127) / 128);
        sgemm1_kernel<<<grid, 256>>>(x, W1, h1hp, a_src1, a_dst1, N_NODES);
    }
    cudaStreamWaitEvent(0, evJoin, 0);
    gat1_kernel<<<(N_NODES + 7) / 8, 256>>>(b1);

    // ---- default: GEMM2 (+fused attn2), gat2 ----
    {
        dim3 grid(C2 / 32, (N_NODES + 255) / 256);
        sgemm2_kernel<<<grid, 256>>>(h1rhp, W2, h2hp, a_src2, a_dst2, N_NODES);
    }
    gat2_kernel<<<(N_NODES + 7) / 8, 256>>>(b2);

    // MLP head
    mlp_kernel<<<NUM_GRAPHS, 192>>>(fc1_w, fc1_b, fc2_w, fc2_b, out);
}

// round 15
// speedup vs baseline: 1.0319x; 1.0045x over previous
#include <cuda_runtime.h>
#include <cuda_fp16.h>
#include <math.h>

#define N_NODES 100000
#define NUM_GRAPHS 128
#define H1 4
#define C1 48
#define F1 192   // H1*C1
#define C2 96
#define D_IN 128
#define NEG_SLOPE 0.2f
#define E_MAX 1750000   // raw edges (1.6M) + self loops (100k) with slack

// ---------------- scratch (device globals; no allocation) ----------------
__device__ __half g_h1h[N_NODES * F1];      // fp16 gather table (layer 1)
__device__ __half g_h1rh[N_NODES * F1];     // layer1 output (relu'd, fp16 -> GEMM2 A)
__device__ __half g_h2h[N_NODES * C2];      // fp16 gather table (layer 2)
__device__ float g_asrc1[N_NODES * H1];
__device__ float g_adst1[N_NODES * H1];
__device__ float g_asrc2[N_NODES];
__device__ float g_adst2[N_NODES];
__device__ float g_pool[NUM_GRAPHS * C2];
__device__ float g_cnt[NUM_GRAPHS];
__device__ int g_src[E_MAX];
__device__ int g_dst[E_MAX];
__device__ int g_batch[N_NODES];
__device__ int g_is64;
__device__ int g_deg[N_NODES];
__device__ int g_off[N_NODES + 1];
__device__ int g_cur[N_NODES];
__device__ int g_csr_src[E_MAX];

__device__ __forceinline__ float leaky(float s) {
    return s > 0.0f ? s : NEG_SLOPE * s;
}

// ---------------- init (zero counters only; stream B) ----------------
__global__ void init_kernel() {
    int i = blockIdx.x * blockDim.x + threadIdx.x;
    int stride = gridDim.x * blockDim.x;
    for (int k = i; k < N_NODES; k += stride) g_deg[k] = 0;
    for (int k = i; k < NUM_GRAPHS * C2; k += stride) g_pool[k] = 0.0f;
    for (int k = i; k < NUM_GRAPHS; k += stride) g_cnt[k] = 0.0f;
}

// zero attention accumulators (default stream, before GEMM1)
__global__ void zero_attn_kernel() {
    int i = blockIdx.x * blockDim.x + threadIdx.x;
    if (i < N_NODES * H1) {
        g_asrc1[i] = 0.0f;
        g_adst1[i] = 0.0f;
    }
    if (i < N_NODES) {
        g_asrc2[i] = 0.0f;
        g_adst2[i] = 0.0f;
    }
}

// ---------------- dtype sniff: int64 vs int32 index buffers ----------------
__global__ void sniff_kernel(const unsigned int* __restrict__ w) {
    __shared__ int any_nonzero;
    if (threadIdx.x == 0) any_nonzero = 0;
    __syncthreads();
    for (int i = threadIdx.x; i < 256; i += blockDim.x) {
        if (w[2 * i + 1] != 0u) any_nonzero = 1;
    }
    __syncthreads();
    if (threadIdx.x == 0) g_is64 = (any_nonzero == 0) ? 1 : 0;
}

__global__ void decode_edges(const void* __restrict__ ei_raw, int E0) {
    int e = blockIdx.x * blockDim.x + threadIdx.x;
    int Etot = E0 + N_NODES;
    if (e >= Etot) return;
    int src, dst;
    if (e < E0) {
        if (g_is64) {
            const long long* p = (const long long*)ei_raw;
            src = (int)p[e];
            dst = (int)p[E0 + e];
        } else {
            const int* p = (const int*)ei_raw;
            src = p[e];
            dst = p[E0 + e];
        }
    } else {
        src = dst = e - E0;
    }
    g_src[e] = src;
    g_dst[e] = dst;
    atomicAdd(&g_deg[dst], 1);
}

__global__ void decode_batch(const void* __restrict__ b_raw) {
    __shared__ int hist[NUM_GRAPHS];
    for (int i = threadIdx.x; i < NUM_GRAPHS; i += blockDim.x) hist[i] = 0;
    __syncthreads();
    int n = blockIdx.x * blockDim.x + threadIdx.x;
    if (n < N_NODES) {
        int b = g_is64 ? (int)((const long long*)b_raw)[n] : ((const int*)b_raw)[n];
        g_batch[n] = b;
        atomicAdd(&hist[b], 1);
    }
    __syncthreads();
    for (int i = threadIdx.x; i < NUM_GRAPHS; i += blockDim.x)
        if (hist[i]) atomicAdd(&g_cnt[i], (float)hist[i]);
}

__global__ void scan_kernel() {
    __shared__ int part[1024];
    int t = threadIdx.x;
    const int CH = (N_NODES + 1023) / 1024;
    int lo = t * CH, hi = min(lo + CH, N_NODES);
    int s = 0;
    for (int i = lo; i < hi; i++) s += g_deg[i];
    part[t] = s;
    __syncthreads();
    for (int o = 1; o < 1024; o <<= 1) {
        int v = (t >= o) ? part[t - o] : 0;
        __syncthreads();
        part[t] += v;
        __syncthreads();
    }
    int base = (t > 0) ? part[t - 1] : 0;
    for (int i = lo; i < hi; i++) {
        g_off[i] = base;
        g_cur[i] = base;
        base += g_deg[i];
    }
    if (t == 1023) g_off[N_NODES] = part[1023];
}

__global__ void scatter_kernel(int Etot) {
    int e = blockIdx.x * blockDim.x + threadIdx.x;
    if (e >= Etot) return;
    int pos = atomicAdd(&g_cur[g_dst[e]], 1);
    g_csr_src[pos] = g_src[e];
}

// ---------------- GEMM1: [M,128]@[128,192] -> fp16 table + fused attn1 ------
__global__ void __launch_bounds__(256) sgemm1_kernel(const float* __restrict__ A,
                                                     const float* __restrict__ B,
                                                     __half* __restrict__ Ch,
                                                     const float* __restrict__ a_src,
                                                     const float* __restrict__ a_dst,
                                                     int M) {
    const int TBM = 128, TBN = 64, TBK = 32, N = F1, K = D_IN;
    __shared__ float As[TBK][TBM + 4];   // reused for attn reduce
    __shared__ float Bs[TBK][TBN + 4];

    int tid = threadIdx.x;
    int row0 = blockIdx.y * TBM;
    int col0 = blockIdx.x * TBN;
    int tx = tid % 16;
    int ty = tid / 16;

    float acc[8][4];
#pragma unroll
    for (int i = 0; i < 8; i++)
#pragma unroll
        for (int j = 0; j < 4; j++) acc[i][j] = 0.0f;

    for (int k0 = 0; k0 < K; k0 += TBK) {
#pragma unroll
        for (int it = 0; it < 4; it++) {
            int idA = tid + it * 256;
            int kc = idA % 8;
            int r = idA / 8;
            int gr = row0 + r;
            float4 v = (gr < M) ? *(const float4*)&A[(size_t)gr * K + k0 + kc * 4]
                                : make_float4(0.f, 0.f, 0.f, 0.f);
            As[kc * 4 + 0][r] = v.x;
            As[kc * 4 + 1][r] = v.y;
            As[kc * 4 + 2][r] = v.z;
            As[kc * 4 + 3][r] = v.w;
        }
#pragma unroll
        for (int it = 0; it < 2; it++) {
            int idB = tid + it * 256;
            int c4 = idB % 16;
            int r = idB / 16;
            *(float4*)&Bs[r][c4 * 4] = *(const float4*)&B[(size_t)(k0 + r) * N + col0 + c4 * 4];
        }
        __syncthreads();

#pragma unroll
        for (int k = 0; k < TBK; k++) {
            float4 a0 = *(const float4*)&As[k][ty * 8];
            float4 a1 = *(const float4*)&As[k][ty * 8 + 4];
            float4 b = *(const float4*)&Bs[k][tx * 4];
            float av[8] = {a0.x, a0.y, a0.z, a0.w, a1.x, a1.y, a1.z, a1.w};
            float bv[4] = {b.x, b.y, b.z, b.w};
#pragma unroll
            for (int i = 0; i < 8; i++)
#pragma unroll
                for (int j = 0; j < 4; j++) acc[i][j] += av[i] * bv[j];
        }
        __syncthreads();
    }

#pragma unroll
    for (int i = 0; i < 8; i++) {
        int gr = row0 + ty * 8 + i;
        if (gr < M) {
            __half2 h01 = __floats2half2_rn(acc[i][0], acc[i][1]);
            __half2 h23 = __floats2half2_rn(acc[i][2], acc[i][3]);
            *(__half2*)&Ch[(size_t)gr * N + col0 + tx * 4] = h01;
            *(__half2*)&Ch[(size_t)gr * N + col0 + tx * 4 + 2] = h23;
        }
    }

    // fused attention partials
    int cbase = col0 + tx * 4;
    float asv[4], adv[4];
#pragma unroll
    for (int j = 0; j < 4; j++) {
        asv[j] = a_src[cbase + j];
        adv[j] = a_dst[cbase + j];
    }
    float* sredS = &As[0][0];          // [128][16]
    float* sredD = sredS + 2048;
#pragma unroll
    for (int i = 0; i < 8; i++) {
        float ps = acc[i][0] * asv[0] + acc[i][1] * asv[1] + acc[i][2] * asv[2] + acc[i][3] * asv[3];
        float pd = acc[i][0] * adv[0] + acc[i][1] * adv[1] + acc[i][2] * adv[2] + acc[i][3] * adv[3];
        sredS[(ty * 8 + i) * 16 + tx] = ps;
        sredD[(ty * 8 + i) * 16 + tx] = pd;
    }
    __syncthreads();

    if (tid < 128) {
        int gr = row0 + tid;
        if (gr < M) {
            int h0 = col0 / 48;
            int gb = (48 * (h0 + 1) - col0) / 4;
            if (gb > 16) gb = 16;
            float s0 = 0.f, d0 = 0.f, s1 = 0.f, d1 = 0.f;
            for (int g = 0; g < gb; g++) {
                s0 += sredS[tid * 16 + g];
                d0 += sredD[tid * 16 + g];
            }
            for (int g = gb; g < 16; g++) {
                s1 += sredS[tid * 16 + g];
                d1 += sredD[tid * 16 + g];
            }
            atomicAdd(&g_asrc1[gr * H1 + h0], s0);
            atomicAdd(&g_adst1[gr * H1 + h0], d0);
            if (gb < 16) {
                atomicAdd(&g_asrc1[gr * H1 + h0 + 1], s1);
                atomicAdd(&g_adst1[gr * H1 + h0 + 1], d1);
            }
        }
    }
}

// ---------------- GEMM2: [M,192](fp16)@[192,96] -> fp16 table + fused attn2 -
__global__ void __launch_bounds__(256) sgemm2_kernel(const __half* __restrict__ A,
                                                     const float* __restrict__ B,
                                                     __half* __restrict__ Ch,
                                                     const float* __restrict__ a_src,
                                                     const float* __restrict__ a_dst,
                                                     int M) {
    const int TBM = 256, TBN = 32, TBK = 32, N = C2, K = F1;
    __shared__ float As[TBK][TBM + 4];
    __shared__ float Bs[TBK][TBN + 4];

    int tid = threadIdx.x;
    int row0 = blockIdx.y * TBM;
    int col0 = blockIdx.x * TBN;
    int tx = tid % 8;
    int ty = tid / 8;

    float acc[8][4];
#pragma unroll
    for (int i = 0; i < 8; i++)
#pragma unroll
        for (int j = 0; j < 4; j++) acc[i][j] = 0.0f;

    for (int k0 = 0; k0 < K; k0 += TBK) {
#pragma unroll
        for (int it = 0; it < 8; it++) {
            int idA = tid + it * 256;
            int kc = idA % 8;
            int r = idA / 8;
            int gr = row0 + r;
            float4 v = make_float4(0.f, 0.f, 0.f, 0.f);
            if (gr < M) {
                const __half2* ap = (const __half2*)&A[(size_t)gr * K + k0 + kc * 4];
                float2 f0 = __half22float2(ap[0]);
                float2 f1 = __half22float2(ap[1]);
                v = make_float4(f0.x, f0.y, f1.x, f1.y);
            }
            As[kc * 4 + 0][r] = v.x;
            As[kc * 4 + 1][r] = v.y;
            As[kc * 4 + 2][r] = v.z;
            As[kc * 4 + 3][r] = v.w;
        }
        {
            int c4 = tid % 8;
            int r = tid / 8;
            *(float4*)&Bs[r][c4 * 4] = *(const float4*)&B[(size_t)(k0 + r) * N + col0 + c4 * 4];
        }
        __syncthreads();

#pragma unroll
        for (int k = 0; k < TBK; k++) {
            float4 a0 = *(const float4*)&As[k][ty * 8];
            float4 a1 = *(const float4*)&As[k][ty * 8 + 4];
            float4 b = *(const float4*)&Bs[k][tx * 4];
            float av[8] = {a0.x, a0.y, a0.z, a0.w, a1.x, a1.y, a1.z, a1.w};
            float bv[4] = {b.x, b.y, b.z, b.w};
#pragma unroll
            for (int i = 0; i < 8; i++)
#pragma unroll
                for (int j = 0; j < 4; j++) acc[i][j] += av[i] * bv[j];
        }
        __syncthreads();
    }

    int cbase = col0 + tx * 4;
    float asv[4], adv[4];
#pragma unroll
    for (int j = 0; j < 4; j++) {
        asv[j] = a_src[cbase + j];
        adv[j] = a_dst[cbase + j];
    }

#pragma unroll
    for (int i = 0; i < 8; i++) {
        int gr = row0 + ty * 8 + i;
        float ps = acc[i][0] * asv[0] + acc[i][1] * asv[1] + acc[i][2] * asv[2] + acc[i][3] * asv[3];
        float pd = acc[i][0] * adv[0] + acc[i][1] * adv[1] + acc[i][2] * adv[2] + acc[i][3] * adv[3];
#pragma unroll
        for (int o = 1; o < 8; o <<= 1) {
            ps += __shfl_xor_sync(0xffffffffu, ps, o);
            pd += __shfl_xor_sync(0xffffffffu, pd, o);
        }
        if (gr < M) {
            __half2 h01 = __floats2half2_rn(acc[i][0], acc[i][1]);
            __half2 h23 = __floats2half2_rn(acc[i][2], acc[i][3]);
            *(__half2*)&Ch[(size_t)gr * N + col0 + tx * 4] = h01;
            *(__half2*)&Ch[(size_t)gr * N + col0 + tx * 4 + 2] = h23;
            if (tx == 0) {
                atomicAdd(&g_asrc2[gr], ps);
                atomicAdd(&g_adst2[gr], pd);
            }
        }
    }
}

// ---------------- layer 1 fused: late-divide softmax, smem transpose --------
// out = (sum_e p_e * h_e) / (sum_e p_e); per 32-edge round:
//   phase1 (edge-parallel): p -> smem, den partials in regs
//   phase2 (channel-parallel): broadcast LDS of p/src, fp16 gathers
__global__ void gat1_kernel(const float* __restrict__ b1) {
    __shared__ float4 sp[8][32];
    __shared__ int ssrc[8][32];
    int node = (blockIdx.x * blockDim.x + threadIdx.x) >> 5;
    int w = (threadIdx.x >> 5) & 7;
    int lane = threadIdx.x & 31;
    if (node >= N_NODES) return;
    int start = g_off[node], end = g_off[node + 1];

    float4 ad = *(const float4*)&g_adst1[node * H1];

    float4 den = make_float4(0.f, 0.f, 0.f, 0.f);
    float acc[6] = {0.f, 0.f, 0.f, 0.f, 0.f, 0.f};

    for (int base = start; base < end; base += 32) {
        int idx = base + lane;
        float4 p = make_float4(0.f, 0.f, 0.f, 0.f);
        int s = 0;
        if (idx < end) {
            s = g_csr_src[idx];
            float4 as = *(const float4*)&g_asrc1[s * H1];
            p.x = __expf(leaky(as.x + ad.x));
            p.y = __expf(leaky(as.y + ad.y));
            p.z = __expf(leaky(as.z + ad.z));
            p.w = __expf(leaky(as.w + ad.w));
            den.x += p.x; den.y += p.y; den.z += p.z; den.w += p.w;
        }
        __syncwarp();            // prior round's phase2 done reading smem
        sp[w][lane] = p;
        ssrc[w][lane] = s;
        __syncwarp();

        int cnt = min(32, end - base);
        for (int j = 0; j < cnt; j++) {
            float4 p4 = sp[w][j];     // broadcast LDS
            int src = ssrc[w][j];     // broadcast LDS
            const __half* hp = &g_h1h[(size_t)src * F1];
#pragma unroll
            for (int k = 0; k < 6; k++) {
                int c = k * 32 + lane;
                float pe = (c < 48) ? p4.x : (c < 96) ? p4.y : (c < 144) ? p4.z : p4.w;
                acc[k] += __half2float(hp[c]) * pe;
            }
        }
    }

#pragma unroll
    for (int o = 16; o > 0; o >>= 1) {
        den.x += __shfl_xor_sync(0xffffffffu, den.x, o);
        den.y += __shfl_xor_sync(0xffffffffu, den.y, o);
        den.z += __shfl_xor_sync(0xffffffffu, den.z, o);
        den.w += __shfl_xor_sync(0xffffffffu, den.w, o);
    }
    float inv0 = 1.0f / den.x, inv1 = 1.0f / den.y, inv2 = 1.0f / den.z, inv3 = 1.0f / den.w;

#pragma unroll
    for (int k = 0; k < 6; k++) {
        int c = k * 32 + lane;
        float inv = (c < 48) ? inv0 : (c < 96) ? inv1 : (c < 144) ? inv2 : inv3;
        g_h1rh[(size_t)node * F1 + c] = __float2half(fmaxf(acc[k] * inv + b1[c], 0.0f));
    }
}

// ---------------- layer 2 fused: late-divide softmax + pool -----------------
__global__ void gat2_kernel(const float* __restrict__ b2) {
    __shared__ float sp[8][32];
    __shared__ int ssrc[8][32];
    int node = (blockIdx.x * blockDim.x + threadIdx.x) >> 5;
    int w = (threadIdx.x >> 5) & 7;
    int lane = threadIdx.x & 31;
    if (node >= N_NODES) return;
    int start = g_off[node], end = g_off[node + 1];

    float ad = g_adst2[node];
    float den = 0.0f;
    float acc[3] = {0.f, 0.f, 0.f};

    for (int base = start; base < end; base += 32) {
        int idx = base + lane;
        float p = 0.0f;
        int s = 0;
        if (idx < end) {
            s = g_csr_src[idx];
            p = __expf(leaky(g_asrc2[s] + ad));
            den += p;
        }
        __syncwarp();
        sp[w][lane] = p;
        ssrc[w][lane] = s;
        __syncwarp();

        int cnt = min(32, end - base);
        for (int j = 0; j < cnt; j++) {
            float pe = sp[w][j];
            int src = ssrc[w][j];
            const __half* hp = &g_h2h[(size_t)src * C2];
#pragma unroll
            for (int k = 0; k < 3; k++) acc[k] += __half2float(hp[k * 32 + lane]) * pe;
        }
    }

#pragma unroll
    for (int o = 16; o > 0; o >>= 1) den += __shfl_xor_sync(0xffffffffu, den, o);
    float inv = 1.0f / den;

    int gp = g_batch[node] * C2;
#pragma unroll
    for (int k = 0; k < 3; k++) {
        int c = k * 32 + lane;
        float v = fmaxf(acc[k] * inv + b2[c], 0.0f);
        atomicAdd(&g_pool[gp + c], v);
    }
}

// ---------------- final MLP: one block per graph ----------------
__global__ void mlp_kernel(const float* __restrict__ fc1_w, const float* __restrict__ fc1_b,
                           const float* __restrict__ fc2_w, const float* __restrict__ fc2_b,
                           float* __restrict__ out) {
    __shared__ float p[C2];
    __shared__ float z[192];
    int g = blockIdx.x;
    int t = threadIdx.x;
    float inv = 1.0f / fmaxf(g_cnt[g], 1.0f);
    if (t < C2) p[t] = g_pool[g * C2 + t] * inv;
    __syncthreads();
    float acc = fc1_b[t];
#pragma unroll
    for (int k = 0; k < C2; k++) acc += p[k] * fc1_w[k * 192 + t];
    z[t] = fmaxf(acc, 0.0f);
    __syncthreads();
    if (t < C2) {
        float o = fc2_b[t];
#pragma unroll
        for (int k = 0; k < 192; k++) o += z[k] * fc2_w[k * C2 + t];
        out[g * C2 + t] = o;
    }
}

// ---------------- host launch (R12-proven two-stream structure) -------------
extern "C" void kernel_launch(void* const* d_in, const int* in_sizes, int n_in,
                              void* d_out, int out_size) {
    const float* x = (const float*)d_in[0];
    const void* ei_raw = d_in[1];
    const void* batch_raw = d_in[2];
    const float* W1 = (const float*)d_in[3];
    const float* a_src1 = (const float*)d_in[4];
    const float* a_dst1 = (const float*)d_in[5];
    const float* b1 = (const float*)d_in[6];
    const float* W2 = (const float*)d_in[7];
    const float* a_src2 = (const float*)d_in[8];
    const float* a_dst2 = (const float*)d_in[9];
    const float* b2 = (const float*)d_in[10];
    const float* fc1_w = (const float*)d_in[11];
    const float* fc1_b = (const float*)d_in[12];
    const float* fc2_w = (const float*)d_in[13];
    const float* fc2_b = (const float*)d_in[14];
    float* out = (float*)d_out;

    int E0 = in_sizes[1] / 2;
    int Etot = E0 + N_NODES;

    __half *h1hp, *h1rhp, *h2hp;
    cudaGetSymbolAddress((void**)&h1hp, g_h1h);
    cudaGetSymbolAddress((void**)&h1rhp, g_h1rh);
    cudaGetSymbolAddress((void**)&h2hp, g_h2h);

    cudaStream_t sB;
    cudaStreamCreateWithFlags(&sB, cudaStreamNonBlocking);
    cudaEvent_t evFork, evJoin;
    cudaEventCreateWithFlags(&evFork, cudaEventDisableTiming);
    cudaEventCreateWithFlags(&evJoin, cudaEventDisableTiming);

    cudaEventRecord(evFork, 0);
    cudaStreamWaitEvent(sB, evFork, 0);

    // ---- stream B: CSR build + batch decode ----
    init_kernel<<<256, 256, 0, sB>>>();
    sniff_kernel<<<1, 256, 0, sB>>>((const unsigned int*)ei_raw);
    decode_edges<<<(Etot + 255) / 256, 256, 0, sB>>>(ei_raw, E0);
    decode_batch<<<(N_NODES + 255) / 256, 256, 0, sB>>>(batch_raw);
    scan_kernel<<<1, 1024, 0, sB>>>();
    scatter_kernel<<<(Etot + 255) / 256, 256, 0, sB>>>(Etot);
    cudaEventRecord(evJoin, sB);

    // ---- default: zero attn accumulators, GEMM1 (+fused attn1) ----
    zero_attn_kernel<<<(N_NODES * H1 + 255) / 256, 256>>>();
    {
        dim3 grid(F1 / 64, (N_NODES + 127) / 128);
        sgemm1_kernel<<<grid, 256>>>(x, W1, h1hp, a_src1, a_dst1, N_NODES);
    }
    cudaStreamWaitEvent(0, evJoin, 0);
    gat1_kernel<<<(N_NODES + 7) / 8, 256>>>(b1);

    // ---- default: GEMM2 (+fused attn2), gat2 ----
    {
        dim3 grid(C2 / 32, (N_NODES + 255) / 256);
        sgemm2_kernel<<<grid, 256>>>(h1rhp, W2, h2hp, a_src2, a_dst2, N_NODES);
    }
    gat2_kernel<<<(N_NODES + 7) / 8, 256>>>(b2);

    // MLP head
    mlp_kernel<<<NUM_GRAPHS, 192>>>(fc1_w, fc1_b, fc2_w, fc2_b, out);
}

// round 16
// speedup vs baseline: 1.1117x; 1.0773x over previous
#include <cuda_runtime.h>
#include <cuda_fp16.h>
#include <mma.h>
#include <math.h>

using namespace nvcuda;

#define N_NODES 100000
#define NUM_GRAPHS 128
#define H1 4
#define C1 48
#define F1 192   // H1*C1
#define C2 96
#define D_IN 128
#define NEG_SLOPE 0.2f
#define E_MAX 1750000   // raw edges (1.6M) + self loops (100k) with slack

// ---------------- scratch (device globals; no allocation) ----------------
__device__ __half g_h1h[N_NODES * F1];      // fp16 gather table (layer 1)
__device__ __half g_h1rh[N_NODES * F1];     // layer1 output (relu'd, fp16 -> GEMM2 A)
__device__ __half g_h2h[N_NODES * C2];      // fp16 gather table (layer 2)
__device__ float g_asrc1[N_NODES * H1];
__device__ float g_adst1[N_NODES * H1];
__device__ float g_asrc2[N_NODES];
__device__ float g_adst2[N_NODES];
__device__ float g_pool[NUM_GRAPHS * C2];
__device__ float g_cnt[NUM_GRAPHS];
__device__ int g_src[E_MAX];
__device__ int g_dst[E_MAX];
__device__ int g_batch[N_NODES];
__device__ int g_is64;
__device__ int g_deg[N_NODES];
__device__ int g_off[N_NODES + 1];
__device__ int g_cur[N_NODES];
__device__ int g_csr_src[E_MAX];

__device__ __forceinline__ float leaky(float s) {
    return s > 0.0f ? s : NEG_SLOPE * s;
}

// ---------------- init (zero counters only; stream B) ----------------
__global__ void init_kernel() {
    int i = blockIdx.x * blockDim.x + threadIdx.x;
    int stride = gridDim.x * blockDim.x;
    for (int k = i; k < N_NODES; k += stride) g_deg[k] = 0;
    for (int k = i; k < NUM_GRAPHS * C2; k += stride) g_pool[k] = 0.0f;
    for (int k = i; k < NUM_GRAPHS; k += stride) g_cnt[k] = 0.0f;
}

// zero attention accumulators (default stream, before GEMM1)
__global__ void zero_attn_kernel() {
    int i = blockIdx.x * blockDim.x + threadIdx.x;
    if (i < N_NODES * H1) {
        g_asrc1[i] = 0.0f;
        g_adst1[i] = 0.0f;
    }
    if (i < N_NODES) {
        g_asrc2[i] = 0.0f;
        g_adst2[i] = 0.0f;
    }
}

// ---------------- dtype sniff: int64 vs int32 index buffers ----------------
__global__ void sniff_kernel(const unsigned int* __restrict__ w) {
    __shared__ int any_nonzero;
    if (threadIdx.x == 0) any_nonzero = 0;
    __syncthreads();
    for (int i = threadIdx.x; i < 256; i += blockDim.x) {
        if (w[2 * i + 1] != 0u) any_nonzero = 1;
    }
    __syncthreads();
    if (threadIdx.x == 0) g_is64 = (any_nonzero == 0) ? 1 : 0;
}

__global__ void decode_edges(const void* __restrict__ ei_raw, int E0) {
    int e = blockIdx.x * blockDim.x + threadIdx.x;
    int Etot = E0 + N_NODES;
    if (e >= Etot) return;
    int src, dst;
    if (e < E0) {
        if (g_is64) {
            const long long* p = (const long long*)ei_raw;
            src = (int)p[e];
            dst = (int)p[E0 + e];
        } else {
            const int* p = (const int*)ei_raw;
            src = p[e];
            dst = p[E0 + e];
        }
    } else {
        src = dst = e - E0;
    }
    g_src[e] = src;
    g_dst[e] = dst;
    atomicAdd(&g_deg[dst], 1);
}

__global__ void decode_batch(const void* __restrict__ b_raw) {
    __shared__ int hist[NUM_GRAPHS];
    for (int i = threadIdx.x; i < NUM_GRAPHS; i += blockDim.x) hist[i] = 0;
    __syncthreads();
    int n = blockIdx.x * blockDim.x + threadIdx.x;
    if (n < N_NODES) {
        int b = g_is64 ? (int)((const long long*)b_raw)[n] : ((const int*)b_raw)[n];
        g_batch[n] = b;
        atomicAdd(&hist[b], 1);
    }
    __syncthreads();
    for (int i = threadIdx.x; i < NUM_GRAPHS; i += blockDim.x)
        if (hist[i]) atomicAdd(&g_cnt[i], (float)hist[i]);
}

__global__ void scan_kernel() {
    __shared__ int part[1024];
    int t = threadIdx.x;
    const int CH = (N_NODES + 1023) / 1024;
    int lo = t * CH, hi = min(lo + CH, N_NODES);
    int s = 0;
    for (int i = lo; i < hi; i++) s += g_deg[i];
    part[t] = s;
    __syncthreads();
    for (int o = 1; o < 1024; o <<= 1) {
        int v = (t >= o) ? part[t - o] : 0;
        __syncthreads();
        part[t] += v;
        __syncthreads();
    }
    int base = (t > 0) ? part[t - 1] : 0;
    for (int i = lo; i < hi; i++) {
        g_off[i] = base;
        g_cur[i] = base;
        base += g_deg[i];
    }
    if (t == 1023) g_off[N_NODES] = part[1023];
}

__global__ void scatter_kernel(int Etot) {
    int e = blockIdx.x * blockDim.x + threadIdx.x;
    if (e >= Etot) return;
    int pos = atomicAdd(&g_cur[g_dst[e]], 1);
    g_csr_src[pos] = g_src[e];
}

// ---------------- GEMM1: [M,128]@[128,192] -> fp16 table + fused attn1 ------
__global__ void __launch_bounds__(256) sgemm1_kernel(const float* __restrict__ A,
                                                     const float* __restrict__ B,
                                                     __half* __restrict__ Ch,
                                                     const float* __restrict__ a_src,
                                                     const float* __restrict__ a_dst,
                                                     int M) {
    const int TBM = 128, TBN = 64, TBK = 32, N = F1, K = D_IN;
    __shared__ float As[TBK][TBM + 4];   // reused for attn reduce
    __shared__ float Bs[TBK][TBN + 4];

    int tid = threadIdx.x;
    int row0 = blockIdx.y * TBM;
    int col0 = blockIdx.x * TBN;
    int tx = tid % 16;
    int ty = tid / 16;

    float acc[8][4];
#pragma unroll
    for (int i = 0; i < 8; i++)
#pragma unroll
        for (int j = 0; j < 4; j++) acc[i][j] = 0.0f;

    for (int k0 = 0; k0 < K; k0 += TBK) {
#pragma unroll
        for (int it = 0; it < 4; it++) {
            int idA = tid + it * 256;
            int kc = idA % 8;
            int r = idA / 8;
            int gr = row0 + r;
            float4 v = (gr < M) ? *(const float4*)&A[(size_t)gr * K + k0 + kc * 4]
                                : make_float4(0.f, 0.f, 0.f, 0.f);
            As[kc * 4 + 0][r] = v.x;
            As[kc * 4 + 1][r] = v.y;
            As[kc * 4 + 2][r] = v.z;
            As[kc * 4 + 3][r] = v.w;
        }
#pragma unroll
        for (int it = 0; it < 2; it++) {
            int idB = tid + it * 256;
            int c4 = idB % 16;
            int r = idB / 16;
            *(float4*)&Bs[r][c4 * 4] = *(const float4*)&B[(size_t)(k0 + r) * N + col0 + c4 * 4];
        }
        __syncthreads();

#pragma unroll
        for (int k = 0; k < TBK; k++) {
            float4 a0 = *(const float4*)&As[k][ty * 8];
            float4 a1 = *(const float4*)&As[k][ty * 8 + 4];
            float4 b = *(const float4*)&Bs[k][tx * 4];
            float av[8] = {a0.x, a0.y, a0.z, a0.w, a1.x, a1.y, a1.z, a1.w};
            float bv[4] = {b.x, b.y, b.z, b.w};
#pragma unroll
            for (int i = 0; i < 8; i++)
#pragma unroll
                for (int j = 0; j < 4; j++) acc[i][j] += av[i] * bv[j];
        }
        __syncthreads();
    }

#pragma unroll
    for (int i = 0; i < 8; i++) {
        int gr = row0 + ty * 8 + i;
        if (gr < M) {
            __half2 h01 = __floats2half2_rn(acc[i][0], acc[i][1]);
            __half2 h23 = __floats2half2_rn(acc[i][2], acc[i][3]);
            *(__half2*)&Ch[(size_t)gr * N + col0 + tx * 4] = h01;
            *(__half2*)&Ch[(size_t)gr * N + col0 + tx * 4 + 2] = h23;
        }
    }

    // fused attention partials
    int cbase = col0 + tx * 4;
    float asv[4], adv[4];
#pragma unroll
    for (int j = 0; j < 4; j++) {
        asv[j] = a_src[cbase + j];
        adv[j] = a_dst[cbase + j];
    }
    float* sredS = &As[0][0];          // [128][16]
    float* sredD = sredS + 2048;
#pragma unroll
    for (int i = 0; i < 8; i++) {
        float ps = acc[i][0] * asv[0] + acc[i][1] * asv[1] + acc[i][2] * asv[2] + acc[i][3] * asv[3];
        float pd = acc[i][0] * adv[0] + acc[i][1] * adv[1] + acc[i][2] * adv[2] + acc[i][3] * adv[3];
        sredS[(ty * 8 + i) * 16 + tx] = ps;
        sredD[(ty * 8 + i) * 16 + tx] = pd;
    }
    __syncthreads();

    if (tid < 128) {
        int gr = row0 + tid;
        if (gr < M) {
            int h0 = col0 / 48;
            int gb = (48 * (h0 + 1) - col0) / 4;
            if (gb > 16) gb = 16;
            float s0 = 0.f, d0 = 0.f, s1 = 0.f, d1 = 0.f;
            for (int g = 0; g < gb; g++) {
                s0 += sredS[tid * 16 + g];
                d0 += sredD[tid * 16 + g];
            }
            for (int g = gb; g < 16; g++) {
                s1 += sredS[tid * 16 + g];
                d1 += sredD[tid * 16 + g];
            }
            atomicAdd(&g_asrc1[gr * H1 + h0], s0);
            atomicAdd(&g_adst1[gr * H1 + h0], d0);
            if (gb < 16) {
                atomicAdd(&g_asrc1[gr * H1 + h0 + 1], s1);
                atomicAdd(&g_adst1[gr * H1 + h0 + 1], d1);
            }
        }
    }
}

// ---------------- GEMM2 (HMMA): [M,192](fp16)@[192,96](fp16) + fused attn2 --
// Block: 128 rows, full N=96. 8 warps; warp w owns rows [w*16, w*16+16),
// 6 m16n16k16 fragments across N. B (W2) converted fp32->fp16 once into smem.
// Epilogue: per-warp store_matrix_sync into smem (overlapping dead B region),
// per-row attn dots + fp16 table stores.
__global__ void __launch_bounds__(256) hgemm2_kernel(const __half* __restrict__ A,
                                                     const float* __restrict__ B,
                                                     __half* __restrict__ Ch,
                                                     const float* __restrict__ a_src,
                                                     const float* __restrict__ a_dst,
                                                     int M) {
    __shared__ __half Bsm[F1 * C2];      // 36864 B; reused as epilogue stage
    __shared__ __half Asm[128 * 16];     // 4096 B

    int tid = threadIdx.x;
    int w = tid >> 5;
    int lane = tid & 31;
    int row0 = blockIdx.x * 128;

    // stage B once (fp32 -> fp16)
    for (int i = tid; i < F1 * C2; i += 256) Bsm[i] = __float2half(B[i]);
    __syncthreads();

    wmma::fragment<wmma::accumulator, 16, 16, 16, float> acc[6];
#pragma unroll
    for (int f = 0; f < 6; f++) wmma::fill_fragment(acc[f], 0.0f);

    for (int k0 = 0; k0 < F1; k0 += 16) {
        // stage A chunk 128x16 (pure fp16 copy, 16B per thread)
        {
            int r = tid >> 1;
            int h8 = (tid & 1) * 8;
            int gr = row0 + r;
            uint4 v = make_uint4(0u, 0u, 0u, 0u);
            if (gr < M) v = *(const uint4*)&A[(size_t)gr * F1 + k0 + h8];
            *(uint4*)&Asm[r * 16 + h8] = v;
        }
        __syncthreads();
        wmma::fragment<wmma::matrix_a, 16, 16, 16, __half, wmma::row_major> af;
        wmma::load_matrix_sync(af, &Asm[(w * 16) * 16], 16);
#pragma unroll
        for (int f = 0; f < 6; f++) {
            wmma::fragment<wmma::matrix_b, 16, 16, 16, __half, wmma::row_major> bf;
            wmma::load_matrix_sync(bf, &Bsm[k0 * C2 + f * 16], C2);
            wmma::mma_sync(acc[f], af, bf, acc[f]);
        }
        __syncthreads();   // Asm rewrite next iter
    }

    // epilogue: Bsm region now dead -> per-warp float[16][20] stage
    float* stage = (float*)Bsm;
    float* ws = stage + w * 320;
    int erow = lane & 15;
    int ehalf = lane >> 4;           // 0: cols 0-7, 1: cols 8-15 of fragment
    int gr = row0 + w * 16 + erow;
    float ps = 0.f, pd = 0.f;

#pragma unroll
    for (int f = 0; f < 6; f++) {
        wmma::store_matrix_sync(ws, acc[f], 20, wmma::mem_row_major);
        __syncwarp();
        int c0 = f * 16 + ehalf * 8;
        const float* rowp = ws + erow * 20 + ehalf * 8;
        __align__(16) __half hbuf[8];
#pragma unroll
        for (int c = 0; c < 8; c++) {
            float v = rowp[c];
            ps += v * a_src[c0 + c];
            pd += v * a_dst[c0 + c];
            hbuf[c] = __float2half(v);
        }
        if (gr < M) *(uint4*)&Ch[(size_t)gr * C2 + c0] = *(uint4*)hbuf;
        __syncwarp();
    }

    ps += __shfl_down_sync(0xffffffffu, ps, 16);
    pd += __shfl_down_sync(0xffffffffu, pd, 16);
    if (lane < 16 && gr < M) {
        atomicAdd(&g_asrc2[gr], ps);
        atomicAdd(&g_adst2[gr], pd);
    }
}

// ---------------- layer 1 fused: late-divide softmax, smem transpose --------
__global__ void gat1_kernel(const float* __restrict__ b1) {
    __shared__ float4 sp[8][32];
    __shared__ int ssrc[8][32];
    int node = (blockIdx.x * blockDim.x + threadIdx.x) >> 5;
    int w = (threadIdx.x >> 5) & 7;
    int lane = threadIdx.x & 31;
    if (node >= N_NODES) return;
    int start = g_off[node], end = g_off[node + 1];

    float4 ad = *(const float4*)&g_adst1[node * H1];

    float4 den = make_float4(0.f, 0.f, 0.f, 0.f);
    float acc[6] = {0.f, 0.f, 0.f, 0.f, 0.f, 0.f};

    for (int base = start; base < end; base += 32) {
        int idx = base + lane;
        float4 p = make_float4(0.f, 0.f, 0.f, 0.f);
        int s = 0;
        if (idx < end) {
            s = g_csr_src[idx];
            float4 as = *(const float4*)&g_asrc1[s * H1];
            p.x = __expf(leaky(as.x + ad.x));
            p.y = __expf(leaky(as.y + ad.y));
            p.z = __expf(leaky(as.z + ad.z));
            p.w = __expf(leaky(as.w + ad.w));
            den.x += p.x; den.y += p.y; den.z += p.z; den.w += p.w;
        }
        __syncwarp();
        sp[w][lane] = p;
        ssrc[w][lane] = s;
        __syncwarp();

        int cnt = min(32, end - base);
        for (int j = 0; j < cnt; j++) {
            float4 p4 = sp[w][j];
            int src = ssrc[w][j];
            const __half* hp = &g_h1h[(size_t)src * F1];
#pragma unroll
            for (int k = 0; k < 6; k++) {
                int c = k * 32 + lane;
                float pe = (c < 48) ? p4.x : (c < 96) ? p4.y : (c < 144) ? p4.z : p4.w;
                acc[k] += __half2float(hp[c]) * pe;
            }
        }
    }

#pragma unroll
    for (int o = 16; o > 0; o >>= 1) {
        den.x += __shfl_xor_sync(0xffffffffu, den.x, o);
        den.y += __shfl_xor_sync(0xffffffffu, den.y, o);
        den.z += __shfl_xor_sync(0xffffffffu, den.z, o);
        den.w += __shfl_xor_sync(0xffffffffu, den.w, o);
    }
    float inv0 = 1.0f / den.x, inv1 = 1.0f / den.y, inv2 = 1.0f / den.z, inv3 = 1.0f / den.w;

#pragma unroll
    for (int k = 0; k < 6; k++) {
        int c = k * 32 + lane;
        float inv = (c < 48) ? inv0 : (c < 96) ? inv1 : (c < 144) ? inv2 : inv3;
        g_h1rh[(size_t)node * F1 + c] = __float2half(fmaxf(acc[k] * inv + b1[c], 0.0f));
    }
}

// ---------------- layer 2 fused: late-divide softmax + pool -----------------
__global__ void gat2_kernel(const float* __restrict__ b2) {
    __shared__ float sp[8][32];
    __shared__ int ssrc[8][32];
    int node = (blockIdx.x * blockDim.x + threadIdx.x) >> 5;
    int w = (threadIdx.x >> 5) & 7;
    int lane = threadIdx.x & 31;
    if (node >= N_NODES) return;
    int start = g_off[node], end = g_off[node + 1];

    float ad = g_adst2[node];
    float den = 0.0f;
    float acc[3] = {0.f, 0.f, 0.f};

    for (int base = start; base < end; base += 32) {
        int idx = base + lane;
        float p = 0.0f;
        int s = 0;
        if (idx < end) {
            s = g_csr_src[idx];
            p = __expf(leaky(g_asrc2[s] + ad));
            den += p;
        }
        __syncwarp();
        sp[w][lane] = p;
        ssrc[w][lane] = s;
        __syncwarp();

        int cnt = min(32, end - base);
        for (int j = 0; j < cnt; j++) {
            float pe = sp[w][j];
            int src = ssrc[w][j];
            const __half* hp = &g_h2h[(size_t)src * C2];
#pragma unroll
            for (int k = 0; k < 3; k++) acc[k] += __half2float(hp[k * 32 + lane]) * pe;
        }
    }

#pragma unroll
    for (int o = 16; o > 0; o >>= 1) den += __shfl_xor_sync(0xffffffffu, den, o);
    float inv = 1.0f / den;

    int gp = g_batch[node] * C2;
#pragma unroll
    for (int k = 0; k < 3; k++) {
        int c = k * 32 + lane;
        float v = fmaxf(acc[k] * inv + b2[c], 0.0f);
        atomicAdd(&g_pool[gp + c], v);
    }
}

// ---------------- final MLP: one block per graph ----------------
__global__ void mlp_kernel(const float* __restrict__ fc1_w, const float* __restrict__ fc1_b,
                           const float* __restrict__ fc2_w, const float* __restrict__ fc2_b,
                           float* __restrict__ out) {
    __shared__ float p[C2];
    __shared__ float z[192];
    int g = blockIdx.x;
    int t = threadIdx.x;
    float inv = 1.0f / fmaxf(g_cnt[g], 1.0f);
    if (t < C2) p[t] = g_pool[g * C2 + t] * inv;
    __syncthreads();
    float acc = fc1_b[t];
#pragma unroll
    for (int k = 0; k < C2; k++) acc += p[k] * fc1_w[k * 192 + t];
    z[t] = fmaxf(acc, 0.0f);
    __syncthreads();
    if (t < C2) {
        float o = fc2_b[t];
#pragma unroll
        for (int k = 0; k < 192; k++) o += z[k] * fc2_w[k * C2 + t];
        out[g * C2 + t] = o;
    }
}

// ---------------- host launch (R12-proven two-stream structure) -------------
extern "C" void kernel_launch(void* const* d_in, const int* in_sizes, int n_in,
                              void* d_out, int out_size) {
    const float* x = (const float*)d_in[0];
    const void* ei_raw = d_in[1];
    const void* batch_raw = d_in[2];
    const float* W1 = (const float*)d_in[3];
    const float* a_src1 = (const float*)d_in[4];
    const float* a_dst1 = (const float*)d_in[5];
    const float* b1 = (const float*)d_in[6];
    const float* W2 = (const float*)d_in[7];
    const float* a_src2 = (const float*)d_in[8];
    const float* a_dst2 = (const float*)d_in[9];
    const float* b2 = (const float*)d_in[10];
    const float* fc1_w = (const float*)d_in[11];
    const float* fc1_b = (const float*)d_in[12];
    const float* fc2_w = (const float*)d_in[13];
    const float* fc2_b = (const float*)d_in[14];
    float* out = (float*)d_out;

    int E0 = in_sizes[1] / 2;
    int Etot = E0 + N_NODES;

    __half *h1hp, *h1rhp, *h2hp;
    cudaGetSymbolAddress((void**)&h1hp, g_h1h);
    cudaGetSymbolAddress((void**)&h1rhp, g_h1rh);
    cudaGetSymbolAddress((void**)&h2hp, g_h2h);

    cudaStream_t sB;
    cudaStreamCreateWithFlags(&sB, cudaStreamNonBlocking);
    cudaEvent_t evFork, evJoin;
    cudaEventCreateWithFlags(&evFork, cudaEventDisableTiming);
    cudaEventCreateWithFlags(&evJoin, cudaEventDisableTiming);

    cudaEventRecord(evFork, 0);
    cudaStreamWaitEvent(sB, evFork, 0);

    // ---- stream B: CSR build + batch decode ----
    init_kernel<<<256, 256, 0, sB>>>();
    sniff_kernel<<<1, 256, 0, sB>>>((const unsigned int*)ei_raw);
    decode_edges<<<(Etot + 255) / 256, 256, 0, sB>>>(ei_raw, E0);
    decode_batch<<<(N_NODES + 255) / 256, 256, 0, sB>>>(batch_raw);
    scan_kernel<<<1, 1024, 0, sB>>>();
    scatter_kernel<<<(Etot + 255) / 256, 256, 0, sB>>>(Etot);
    cudaEventRecord(evJoin, sB);

    // ---- default: zero attn accumulators, GEMM1 (+fused attn1) ----
    zero_attn_kernel<<<(N_NODES * H1 + 255) / 256, 256>>>();
    {
        dim3 grid(F1 / 64, (N_NODES + 127) / 128);
        sgemm1_kernel<<<grid, 256>>>(x, W1, h1hp, a_src1, a_dst1, N_NODES);
    }
    cudaStreamWaitEvent(0, evJoin, 0);
    gat1_kernel<<<(N_NODES + 7) / 8, 256>>>(b1);

    // ---- default: GEMM2 HMMA (+fused attn2), gat2 ----
    hgemm2_kernel<<<(N_NODES + 127) / 128, 256>>>(h1rhp, W2, h2hp, a_src2, a_dst2, N_NODES);
    gat2_kernel<<<(N_NODES + 7) / 8, 256>>>(b2);

    // MLP head
    mlp_kernel<<<NUM_GRAPHS, 192>>>(fc1_w, fc1_b, fc2_w, fc2_b, out);
}